// round 4
// baseline (speedup 1.0000x reference)
#include <cuda_runtime.h>
#include <cuda_bf16.h>

// ---------------------------------------------------------------------------
// mLSTM single step, B=8192, V=50257, E=1024, H=2048, O=2
//   x   = emb[inp]
//   m_t = (x@W_mx^T + b_mx) * (h0@W_mh^T + b_mh)
//   g_z = act(x@W_zx^T + b_zx + m_t@W_zm^T + b_zm)   z in {f,i,o}:sigmoid, c:tanh
//   cx  = f*c0 + i*c~ ; hx = o*tanh(cx) ; out = hx@W_dec^T + b_dec
// d_out layout: [ out(B,2) | hx(B,H) | cx(B,H) ]  (fp32)
//
// Strategy: pre-convert weights/h0 to bf16 once; two fused mma.sync GEMM
// kernels (dual-K accumulation, cp.async 2-stage pipeline); gate kernel
// keeps all 4 gates in registers and writes hx/cx directly to d_out.
// ---------------------------------------------------------------------------

#define B_  8192
#define E_  1024
#define H_  2048
#define MEG (1 << 20)

// bf16 scratch (static __device__ — allocation-free per harness rules)
__device__ __align__(16) __nv_bfloat16 g_xb [(size_t)B_ * E_];   // 16 MB  x (gathered, bf16)
__device__ __align__(16) __nv_bfloat16 g_h0b[(size_t)B_ * H_];   // 32 MB  h0 bf16
__device__ __align__(16) __nv_bfloat16 g_mtb[(size_t)B_ * H_];   // 32 MB  m_t bf16
__device__ __align__(16) __nv_bfloat16 g_wb [(size_t)30 * MEG];  // 60 MB  all weights bf16

// weight offsets inside g_wb (elements)
#define OFF_MX 0
#define OFF_MH (2 * MEG)
#define OFF_ZX(z) (6 * MEG + (size_t)(z) * 6 * MEG)   // z: 0=f 1=i 2=o 3=c  (H x E)
#define OFF_ZM(z) (8 * MEG + (size_t)(z) * 6 * MEG)   //                    (H x H)

// ---------------------------------------------------------------------------
// helpers
// ---------------------------------------------------------------------------
__device__ __forceinline__ unsigned saddr(const void* p) {
    return (unsigned)__cvta_generic_to_shared(p);
}
__device__ __forceinline__ void cpa16(unsigned dst, const void* src) {
    asm volatile("cp.async.cg.shared.global [%0], [%1], 16;\n" :: "r"(dst), "l"(src));
}
__device__ __forceinline__ void cp_commit() {
    asm volatile("cp.async.commit_group;\n" ::);
}
template <int N> __device__ __forceinline__ void cp_wait() {
    asm volatile("cp.async.wait_group %0;\n" :: "n"(N));
}
__device__ __forceinline__ void mma16816(float c[4], const unsigned a[4], const unsigned b[2]) {
    asm volatile(
        "mma.sync.aligned.m16n8k16.row.col.f32.bf16.bf16.f32 "
        "{%0,%1,%2,%3}, {%4,%5,%6,%7}, {%8,%9}, {%0,%1,%2,%3};\n"
        : "+f"(c[0]), "+f"(c[1]), "+f"(c[2]), "+f"(c[3])
        : "r"(a[0]), "r"(a[1]), "r"(a[2]), "r"(a[3]), "r"(b[0]), "r"(b[1]));
}
__device__ __forceinline__ float sigf(float v)  { return 1.f / (1.f + __expf(-v)); }
__device__ __forceinline__ float tanhf_(float v){ return fmaf(2.f, 1.f / (1.f + __expf(-2.f * v)), -1.f); }

// ---------------------------------------------------------------------------
// fp32 -> bf16 conversion (weights + h0), 11 segments in one launch
// ---------------------------------------------------------------------------
struct Cvt { const float* s[11]; __nv_bfloat16* d[11]; int n4[11]; };

__global__ void cvt_f32_bf16(Cvt a) {
    const int seg = blockIdx.y;
    const float4* __restrict__ s = (const float4*)a.s[seg];
    uint2* __restrict__ d = (uint2*)a.d[seg];
    const int n4 = a.n4[seg];
    for (int i = blockIdx.x * blockDim.x + threadIdx.x; i < n4;
         i += gridDim.x * blockDim.x) {
        float4 v = s[i];
        __nv_bfloat162 lo = __float22bfloat162_rn(make_float2(v.x, v.y));
        __nv_bfloat162 hi = __float22bfloat162_rn(make_float2(v.z, v.w));
        uint2 o;
        o.x = *(unsigned*)&lo;
        o.y = *(unsigned*)&hi;
        d[i] = o;
    }
}

// x = bf16(emb[inp]) : one block per row, 256 threads x float4
__global__ void gather_x(const int* __restrict__ inp, const float* __restrict__ emb) {
    const int b = blockIdx.x;
    const int v = inp[b];
    float4 t = ((const float4*)(emb + (size_t)v * E_))[threadIdx.x];
    __nv_bfloat162 lo = __float22bfloat162_rn(make_float2(t.x, t.y));
    __nv_bfloat162 hi = __float22bfloat162_rn(make_float2(t.z, t.w));
    uint2 o;
    o.x = *(unsigned*)&lo;
    o.y = *(unsigned*)&hi;
    ((uint2*)(g_xb + (size_t)b * E_))[threadIdx.x] = o;
}

// ---------------------------------------------------------------------------
// m_t kernel:  m_t = (x@W_mx^T + b_mx) * (h0@W_mh^T + b_mh)   -> g_mtb (bf16)
// BM=128, BN=64, BK=32, 256 thr (8 warps 4x2), warp tile 32x32.
// Unified k loop: tiles [0,32) from x/W_mx (K=1024), [32,96) from h0/W_mh (K=2048).
// ---------------------------------------------------------------------------
#define LDS_ 40   // 32 + 8 bf16 padding
#define NT_TOT 96
#define NT_X   32

__global__ __launch_bounds__(256, 1)
void gemm_mt(const float* __restrict__ b_mx, const float* __restrict__ b_mh) {
    __shared__ __align__(16) __nv_bfloat16 As[2][128 * LDS_];
    __shared__ __align__(16) __nv_bfloat16 Bs[2][64 * LDS_];

    const int m0 = blockIdx.y * 128;
    const int n0 = blockIdx.x * 64;
    const int tid = threadIdx.x, lane = tid & 31, warp = tid >> 5;
    const int wm = warp & 3, wn = warp >> 2, g = lane >> 2, ti = lane & 3;

    float ax[2][4][4], ah[2][4][4];
#pragma unroll
    for (int mt = 0; mt < 2; mt++)
#pragma unroll
        for (int nt = 0; nt < 4; nt++)
#pragma unroll
            for (int j = 0; j < 4; j++) { ax[mt][nt][j] = 0.f; ah[mt][nt][j] = 0.f; }

    auto issue = [&](int t, int s) {
        const __nv_bfloat16 *Ab, *Wb;
        int ld, tt = t;
        if (t < NT_X) { Ab = g_xb;  Wb = g_wb + OFF_MX; ld = E_; }
        else          { Ab = g_h0b; Wb = g_wb + OFF_MH; ld = H_; tt = t - NT_X; }
        const int k0 = tt * 32;
#pragma unroll
        for (int i = 0; i < 2; i++) {
            int lin = tid + i * 256, r = lin >> 2, c = lin & 3;
            cpa16(saddr(&As[s][r * LDS_ + c * 8]),
                  Ab + (size_t)(m0 + r) * ld + k0 + c * 8);
        }
        {
            int r = tid >> 2, c = tid & 3;
            cpa16(saddr(&Bs[s][r * LDS_ + c * 8]),
                  Wb + (size_t)(n0 + r) * ld + k0 + c * 8);
        }
        cp_commit();
    };

    issue(0, 0);
    for (int t = 0; t < NT_TOT; t++) {
        if (t + 1 < NT_TOT) { issue(t + 1, (t + 1) & 1); cp_wait<1>(); }
        else                { cp_wait<0>(); }
        __syncthreads();
        const int st = t & 1;
        const bool px = (t < NT_X);
#pragma unroll
        for (int ks = 0; ks < 2; ks++) {
            const int kb = ks * 16 + ti * 2;
            unsigned af[2][4], bf[4][2];
#pragma unroll
            for (int mt = 0; mt < 2; mt++) {
                const __nv_bfloat16* p = &As[st][(wm * 32 + mt * 16 + g) * LDS_ + kb];
                af[mt][0] = *(const unsigned*)(p);
                af[mt][1] = *(const unsigned*)(p + 8 * LDS_);
                af[mt][2] = *(const unsigned*)(p + 8);
                af[mt][3] = *(const unsigned*)(p + 8 * LDS_ + 8);
            }
#pragma unroll
            for (int nt = 0; nt < 4; nt++) {
                const __nv_bfloat16* p = &Bs[st][(wn * 32 + nt * 8 + g) * LDS_ + kb];
                bf[nt][0] = *(const unsigned*)(p);
                bf[nt][1] = *(const unsigned*)(p + 8);
            }
            if (px) {
#pragma unroll
                for (int mt = 0; mt < 2; mt++)
#pragma unroll
                    for (int nt = 0; nt < 4; nt++) mma16816(ax[mt][nt], af[mt], bf[nt]);
            } else {
#pragma unroll
                for (int mt = 0; mt < 2; mt++)
#pragma unroll
                    for (int nt = 0; nt < 4; nt++) mma16816(ah[mt][nt], af[mt], bf[nt]);
            }
        }
        __syncthreads();
    }

#pragma unroll
    for (int mt = 0; mt < 2; mt++)
#pragma unroll
        for (int nt = 0; nt < 4; nt++) {
            const int gm = m0 + wm * 32 + mt * 16 + g;
            const int gn = n0 + wn * 32 + nt * 8 + ti * 2;
#pragma unroll
            for (int h = 0; h < 2; h++) {
                const int gm2 = gm + h * 8;
#pragma unroll
                for (int j = 0; j < 2; j++) {
                    const int n = gn + j;
                    float v = (ax[mt][nt][h * 2 + j] + __ldg(b_mx + n)) *
                              (ah[mt][nt][h * 2 + j] + __ldg(b_mh + n));
                    g_mtb[(size_t)gm2 * H_ + n] = __float2bfloat16(v);
                }
            }
        }
}

// ---------------------------------------------------------------------------
// gates kernel: all 4 gates per block tile, dual-K (x then m_t), epilogue
// computes cx/hx directly into d_out.
// Dynamic smem: As 2x128x40 | Bs 2x4x64x40 | bias sums 4x64 f32  = 62464 B
// ---------------------------------------------------------------------------
#define GATES_SMEM (61440 + 1024)

__global__ __launch_bounds__(256, 1)
void gemm_gates(const float* __restrict__ bfx, const float* __restrict__ bfm,
                const float* __restrict__ bix, const float* __restrict__ bim,
                const float* __restrict__ box_, const float* __restrict__ bom,
                const float* __restrict__ bcx, const float* __restrict__ bcm,
                const float* __restrict__ c0,
                float* __restrict__ hx, float* __restrict__ cx) {
    extern __shared__ __align__(16) __nv_bfloat16 sm[];
    // layout (bf16 elements)
    //   As(s):   s*5120                (2 x 128*40)
    //   Bs(s,z): 10240 + (s*4+z)*2560  (2 x 4 x 64*40)
    //   bias:    float* at elem 30720  (4 x 64 floats)
    auto As = [&](int s) { return sm + (size_t)s * (128 * LDS_); };
    auto Bsz = [&](int s, int z) { return sm + 10240 + (size_t)(s * 4 + z) * (64 * LDS_); };
    float* bs = (float*)(sm + 30720);

    const int m0 = blockIdx.y * 128;
    const int n0 = blockIdx.x * 64;
    const int tid = threadIdx.x, lane = tid & 31, warp = tid >> 5;
    const int wm = warp & 3, wn = warp >> 2, g = lane >> 2, ti = lane & 3;

    if (tid < 64) {
        const int n = n0 + tid;
        bs[0 * 64 + tid] = bfx[n] + bfm[n];
        bs[1 * 64 + tid] = bix[n] + bim[n];
        bs[2 * 64 + tid] = box_[n] + bom[n];
        bs[3 * 64 + tid] = bcx[n] + bcm[n];
    }

    float acc[4][2][4][4];
#pragma unroll
    for (int z = 0; z < 4; z++)
#pragma unroll
        for (int mt = 0; mt < 2; mt++)
#pragma unroll
            for (int nt = 0; nt < 4; nt++)
#pragma unroll
                for (int j = 0; j < 4; j++) acc[z][mt][nt][j] = 0.f;

    auto issue = [&](int t, int s) {
        const __nv_bfloat16* Ab;
        int ld, tt = t;
        bool xph = (t < NT_X);
        if (xph) { Ab = g_xb;  ld = E_; }
        else     { Ab = g_mtb; ld = H_; tt = t - NT_X; }
        const int k0 = tt * 32;
#pragma unroll
        for (int i = 0; i < 2; i++) {
            int lin = tid + i * 256, r = lin >> 2, c = lin & 3;
            cpa16(saddr(As(s) + r * LDS_ + c * 8),
                  Ab + (size_t)(m0 + r) * ld + k0 + c * 8);
        }
#pragma unroll
        for (int i = 0; i < 4; i++) {
            int lin = tid + i * 256;
            int z = lin >> 8, rr = (lin & 255) >> 2, cc = lin & 3;
            const __nv_bfloat16* Wb = g_wb + (xph ? OFF_ZX(z) : OFF_ZM(z));
            cpa16(saddr(Bsz(s, z) + rr * LDS_ + cc * 8),
                  Wb + (size_t)(n0 + rr) * ld + k0 + cc * 8);
        }
        cp_commit();
    };

    issue(0, 0);
    for (int t = 0; t < NT_TOT; t++) {
        if (t + 1 < NT_TOT) { issue(t + 1, (t + 1) & 1); cp_wait<1>(); }
        else                { cp_wait<0>(); }
        __syncthreads();
        const int st = t & 1;
#pragma unroll
        for (int ks = 0; ks < 2; ks++) {
            const int kb = ks * 16 + ti * 2;
            unsigned af[2][4];
#pragma unroll
            for (int mt = 0; mt < 2; mt++) {
                const __nv_bfloat16* p = As(st) + (wm * 32 + mt * 16 + g) * LDS_ + kb;
                af[mt][0] = *(const unsigned*)(p);
                af[mt][1] = *(const unsigned*)(p + 8 * LDS_);
                af[mt][2] = *(const unsigned*)(p + 8);
                af[mt][3] = *(const unsigned*)(p + 8 * LDS_ + 8);
            }
#pragma unroll
            for (int z = 0; z < 4; z++) {
                unsigned bf[4][2];
#pragma unroll
                for (int nt = 0; nt < 4; nt++) {
                    const __nv_bfloat16* p = Bsz(st, z) + (wn * 32 + nt * 8 + g) * LDS_ + kb;
                    bf[nt][0] = *(const unsigned*)(p);
                    bf[nt][1] = *(const unsigned*)(p + 8);
                }
#pragma unroll
                for (int mt = 0; mt < 2; mt++)
#pragma unroll
                    for (int nt = 0; nt < 4; nt++) mma16816(acc[z][mt][nt], af[mt], bf[nt]);
            }
        }
        __syncthreads();
    }

    // epilogue: gates -> cx, hx
#pragma unroll
    for (int mt = 0; mt < 2; mt++)
#pragma unroll
        for (int nt = 0; nt < 4; nt++) {
            const int gm = m0 + wm * 32 + mt * 16 + g;
            const int nl0 = wn * 32 + nt * 8 + ti * 2;
#pragma unroll
            for (int h = 0; h < 2; h++) {
                const int gm2 = gm + h * 8;
#pragma unroll
                for (int j = 0; j < 2; j++) {
                    const int nl = nl0 + j;
                    const int n = n0 + nl;
                    const int e = h * 2 + j;
                    float fg = sigf(acc[0][mt][nt][e] + bs[0 * 64 + nl]);
                    float ig = sigf(acc[1][mt][nt][e] + bs[1 * 64 + nl]);
                    float og = sigf(acc[2][mt][nt][e] + bs[2 * 64 + nl]);
                    float ct = tanhf_(acc[3][mt][nt][e] + bs[3 * 64 + nl]);
                    float c0v = __ldg(c0 + (size_t)gm2 * H_ + n);
                    float cv = fg * c0v + ig * ct;
                    float hv = og * tanhf_(cv);
                    hx[(size_t)gm2 * H_ + n] = hv;
                    cx[(size_t)gm2 * H_ + n] = cv;
                }
            }
        }
}

// ---------------------------------------------------------------------------
// decoder: out[b, 0:2] = hx[b] @ W_dec^T + b_dec   (warp per row)
// ---------------------------------------------------------------------------
__global__ void decoder(const float* __restrict__ hx, const float* __restrict__ Wd,
                        const float* __restrict__ bd, float* __restrict__ out) {
    const int gw = (blockIdx.x * blockDim.x + threadIdx.x) >> 5;
    const int lane = threadIdx.x & 31;
    if (gw >= B_) return;
    const float4* h4 = (const float4*)(hx + (size_t)gw * H_);
    const float4* w0 = (const float4*)(Wd);
    const float4* w1 = (const float4*)(Wd + H_);
    float s0 = 0.f, s1 = 0.f;
    for (int i = lane; i < H_ / 4; i += 32) {
        float4 h = h4[i], a = w0[i], b = w1[i];
        s0 += h.x * a.x + h.y * a.y + h.z * a.z + h.w * a.w;
        s1 += h.x * b.x + h.y * b.y + h.z * b.z + h.w * b.w;
    }
#pragma unroll
    for (int o = 16; o; o >>= 1) {
        s0 += __shfl_xor_sync(0xFFFFFFFFu, s0, o);
        s1 += __shfl_xor_sync(0xFFFFFFFFu, s1, o);
    }
    if (lane == 0) {
        out[(size_t)gw * 2 + 0] = s0 + bd[0];
        out[(size_t)gw * 2 + 1] = s1 + bd[1];
    }
}

// ---------------------------------------------------------------------------
extern "C" void kernel_launch(void* const* d_in, const int* in_sizes, int n_in,
                              void* d_out, int out_size) {
    const int*   inp  = (const int*)  d_in[0];
    const float* h0   = (const float*)d_in[1];
    const float* c0   = (const float*)d_in[2];
    const float* emb  = (const float*)d_in[3];
    const float *W_mx = (const float*)d_in[4],  *b_mx = (const float*)d_in[5];
    const float *W_mh = (const float*)d_in[6],  *b_mh = (const float*)d_in[7];
    const float *W_fx = (const float*)d_in[8],  *b_fx = (const float*)d_in[9];
    const float *W_fm = (const float*)d_in[10], *b_fm = (const float*)d_in[11];
    const float *W_ix = (const float*)d_in[12], *b_ix = (const float*)d_in[13];
    const float *W_im = (const float*)d_in[14], *b_im = (const float*)d_in[15];
    const float *W_ox = (const float*)d_in[16], *b_ox = (const float*)d_in[17];
    const float *W_om = (const float*)d_in[18], *b_om = (const float*)d_in[19];
    const float *W_cx = (const float*)d_in[20], *b_cx = (const float*)d_in[21];
    const float *W_cm = (const float*)d_in[22], *b_cm = (const float*)d_in[23];
    const float *W_dec= (const float*)d_in[24], *b_dec= (const float*)d_in[25];
    float* out = (float*)d_out;

    __nv_bfloat16* wb;
    __nv_bfloat16* h0b;
    cudaGetSymbolAddress((void**)&wb,  g_wb);
    cudaGetSymbolAddress((void**)&h0b, g_h0b);

    // 1) convert weights + h0 to bf16 (one launch, 11 segments)
    Cvt cv;
    const float* srcs[11] = {W_mx, W_mh, W_fx, W_fm, W_ix, W_im, W_ox, W_om, W_cx, W_cm, h0};
    const size_t offs[11] = {OFF_MX, OFF_MH,
                             OFF_ZX(0), OFF_ZM(0), OFF_ZX(1), OFF_ZM(1),
                             OFF_ZX(2), OFF_ZM(2), OFF_ZX(3), OFF_ZM(3), 0};
    const int cnts[11] = {2*MEG, 4*MEG, 2*MEG, 4*MEG, 2*MEG, 4*MEG,
                          2*MEG, 4*MEG, 2*MEG, 4*MEG, 16*MEG};
    for (int i = 0; i < 11; i++) {
        cv.s[i] = srcs[i];
        cv.d[i] = (i == 10) ? h0b : (wb + offs[i]);
        cv.n4[i] = cnts[i] / 4;
    }
    cvt_f32_bf16<<<dim3(1024, 11), 256>>>(cv);

    // 2) x = bf16(emb[inp])
    gather_x<<<B_, 256>>>(inp, emb);

    // 3) m_t
    gemm_mt<<<dim3(H_ / 64, B_ / 128), 256>>>(b_mx, b_mh);

    // 4) gates + cx/hx fused, written straight into d_out
    float* hx_out = out + 2 * (size_t)B_;
    float* cx_out = hx_out + (size_t)B_ * H_;
    cudaFuncSetAttribute(gemm_gates, cudaFuncAttributeMaxDynamicSharedMemorySize,
                         GATES_SMEM);
    gemm_gates<<<dim3(H_ / 64, B_ / 128), 256, GATES_SMEM>>>(
        b_fx, b_fm, b_ix, b_im, b_ox, b_om, b_cx, b_cm, c0, hx_out, cx_out);

    // 5) out = hx@W_dec^T + b_dec
    decoder<<<(B_ * 32) / 256, 256>>>(hx_out, W_dec, b_dec, out);
}